// round 5
// baseline (speedup 1.0000x reference)
#include <cuda_runtime.h>
#include <math.h>

// OnlineNeuron: T=4 two-compartment SNN recurrence, elementwise, f32.
// Pure HBM-streaming: 256 MB read + 256 MB write, irreducible.
// Round-5: persistent single-wave kernel. 512 CTAs (all resident, zero wave
// transitions), each thread grid-strides exactly 32 float4 tiles with a
// 2-stage software pipeline: next iteration's 4 timestep loads are issued
// before the current iteration's compute+stores, keeping a continuous load
// stream in flight over the store stream.

#define T_STEPS 4

__device__ __forceinline__ float sigmoidf_(float v) {
    return 1.0f / (1.0f + expf(-v));
}

__device__ __forceinline__ void step4(float4& vd, float4& vs, const float4 xt,
                                      float a1, float b1, float a2, float b2,
                                      float4& o)
{
    vd.x = a1 * vd.x + b1 * vs.x + xt.x;
    vd.y = a1 * vd.y + b1 * vs.y + xt.y;
    vd.z = a1 * vd.z + b1 * vs.z + xt.z;
    vd.w = a1 * vd.w + b1 * vs.w + xt.w;

    vs.x = a2 * vs.x + b2 * vd.x;
    vs.y = a2 * vs.y + b2 * vd.y;
    vs.z = a2 * vs.z + b2 * vd.z;
    vs.w = a2 * vs.w + b2 * vd.w;

    o.x = (vs.x >= 1.0f) ? 1.0f : 0.0f;
    o.y = (vs.y >= 1.0f) ? 1.0f : 0.0f;
    o.z = (vs.z >= 1.0f) ? 1.0f : 0.0f;
    o.w = (vs.w >= 1.0f) ? 1.0f : 0.0f;

    vs.x -= o.x;  vs.y -= o.y;  vs.z -= o.z;  vs.w -= o.w;
}

#define GRID_CTAS 512
#define BLOCK     256

__global__ __launch_bounds__(BLOCK, 4)
void online_neuron_kernel(const float4* __restrict__ x,
                          const float* __restrict__ alpha1,
                          const float* __restrict__ beta1,
                          const float* __restrict__ alpha2,
                          const float* __restrict__ beta2,
                          float4* __restrict__ out,
                          int n4)   // float4 count per timestep slab (2^22)
{
    const int step = GRID_CTAS * BLOCK;              // 2^17
    const int iters = n4 / step;                     // 32, exact
    int i = blockIdx.x * BLOCK + threadIdx.x;

    const long long stride = (long long)n4;          // float4s between slabs

    const float a1 = sigmoidf_(__ldg(alpha1)) - 0.5f;
    const float b1 = sigmoidf_(__ldg(beta1))  - 0.5f;
    const float a2 = sigmoidf_(__ldg(alpha2)) + 0.5f;
    const float b2 = sigmoidf_(__ldg(beta2))  + 0.5f;

    // Prologue: load iteration 0's four timestep tiles.
    float4 xt[T_STEPS];
    #pragma unroll
    for (int t = 0; t < T_STEPS; t++)
        xt[t] = __ldcs(&x[(long long)t * stride + i]);

    for (int it = 0; it < iters; it++) {
        const int inext = i + step;

        // Prefetch next iteration's loads before touching xt (2-stage pipe).
        float4 xn[T_STEPS];
        if (it + 1 < iters) {
            #pragma unroll
            for (int t = 0; t < T_STEPS; t++)
                xn[t] = __ldcs(&x[(long long)t * stride + inext]);
        }

        // Recurrence for the current tile.
        float4 vd = make_float4(0.f, 0.f, 0.f, 0.f);
        float4 vs = make_float4(0.5f, 0.5f, 0.5f, 0.5f);
        float4 o[T_STEPS];
        #pragma unroll
        for (int t = 0; t < T_STEPS; t++)
            step4(vd, vs, xt[t], a1, b1, a2, b2, o[t]);

        #pragma unroll
        for (int t = 0; t < T_STEPS; t++)
            __stcs(&out[(long long)t * stride + i], o[t]);

        #pragma unroll
        for (int t = 0; t < T_STEPS; t++)
            xt[t] = xn[t];
        i = inext;
    }
}

extern "C" void kernel_launch(void* const* d_in, const int* in_sizes, int n_in,
                              void* d_out, int out_size)
{
    const float* x      = (const float*)d_in[0];
    const float* alpha1 = (const float*)d_in[1];
    const float* beta1  = (const float*)d_in[2];
    const float* alpha2 = (const float*)d_in[3];
    const float* beta2  = (const float*)d_in[4];
    float* out = (float*)d_out;

    const int n_total = in_sizes[0];          // 512*128*32*32 = 67,108,864
    const int n_slab  = n_total / T_STEPS;    // 16,777,216 floats per slab
    const int n4      = n_slab / 4;           // 4,194,304 float4 (2^22)

    online_neuron_kernel<<<GRID_CTAS, BLOCK>>>(
        (const float4*)x, alpha1, beta1, alpha2, beta2, (float4*)out, n4);
}

// round 6
// speedup vs baseline: 1.1534x; 1.1534x over previous
#include <cuda_runtime.h>
#include <math.h>

// OnlineNeuron: T=4 two-compartment SNN recurrence, elementwise, f32.
// Pure HBM-streaming: 256 MB read + 256 MB write, irreducible.
// Final config (= Round-2 winner, block 512): one float4 per thread, all four
// timestep LDG.128s front-batched (per-thread MLP=4), recurrence, four
// back-batched STG.128s. HW-scheduled full grid; streaming cache hints.
// Measured floor ~82 us = ~6.25 TB/s sustained mixed R/W stream; MLP>4,
// 256-bit accesses, persistent grids, and multi-tile threads all regressed
// or were neutral (R3-R5 post-mortems).

#define T_STEPS 4

__device__ __forceinline__ float sigmoidf_(float v) {
    return 1.0f / (1.0f + expf(-v));
}

__global__ __launch_bounds__(512)
void online_neuron_kernel(const float4* __restrict__ x,
                          const float* __restrict__ alpha1,
                          const float* __restrict__ beta1,
                          const float* __restrict__ alpha2,
                          const float* __restrict__ beta2,
                          float4* __restrict__ out,
                          int n4)   // float4 count per timestep slab
{
    int i = blockIdx.x * blockDim.x + threadIdx.x;
    if (i >= n4) return;

    const long long stride = (long long)n4;   // float4 units between timesteps

    // ---- Front-batched loads: 4 independent LDG.128 in flight (MLP=4) ----
    float4 xt[T_STEPS];
    #pragma unroll
    for (int t = 0; t < T_STEPS; t++)
        xt[t] = __ldcs(&x[(long long)t * stride + i]);

    const float a1 = sigmoidf_(__ldg(alpha1)) - 0.5f;
    const float b1 = sigmoidf_(__ldg(beta1))  - 0.5f;
    const float a2 = sigmoidf_(__ldg(alpha2)) + 0.5f;
    const float b2 = sigmoidf_(__ldg(beta2))  + 0.5f;

    float4 vd = make_float4(0.f, 0.f, 0.f, 0.f);
    float4 vs = make_float4(0.5f, 0.5f, 0.5f, 0.5f);

    float4 o[T_STEPS];

    #pragma unroll
    for (int t = 0; t < T_STEPS; t++) {
        vd.x = a1 * vd.x + b1 * vs.x + xt[t].x;
        vd.y = a1 * vd.y + b1 * vs.y + xt[t].y;
        vd.z = a1 * vd.z + b1 * vs.z + xt[t].z;
        vd.w = a1 * vd.w + b1 * vs.w + xt[t].w;

        vs.x = a2 * vs.x + b2 * vd.x;
        vs.y = a2 * vs.y + b2 * vd.y;
        vs.z = a2 * vs.z + b2 * vd.z;
        vs.w = a2 * vs.w + b2 * vd.w;

        o[t].x = (vs.x >= 1.0f) ? 1.0f : 0.0f;
        o[t].y = (vs.y >= 1.0f) ? 1.0f : 0.0f;
        o[t].z = (vs.z >= 1.0f) ? 1.0f : 0.0f;
        o[t].w = (vs.w >= 1.0f) ? 1.0f : 0.0f;

        vs.x -= o[t].x;  vs.y -= o[t].y;  vs.z -= o[t].z;  vs.w -= o[t].w;
    }

    // ---- Back-batched stores ----
    #pragma unroll
    for (int t = 0; t < T_STEPS; t++)
        __stcs(&out[(long long)t * stride + i], o[t]);
}

extern "C" void kernel_launch(void* const* d_in, const int* in_sizes, int n_in,
                              void* d_out, int out_size)
{
    const float* x      = (const float*)d_in[0];
    const float* alpha1 = (const float*)d_in[1];
    const float* beta1  = (const float*)d_in[2];
    const float* alpha2 = (const float*)d_in[3];
    const float* beta2  = (const float*)d_in[4];
    float* out = (float*)d_out;

    const int n_total = in_sizes[0];          // 512*128*32*32 = 67,108,864
    const int n_slab  = n_total / T_STEPS;    // 16,777,216 floats per slab
    const int n4      = n_slab / 4;           // 4,194,304 float4 per slab

    const int block = 512;
    const int grid  = (n4 + block - 1) / block;   // 8192

    online_neuron_kernel<<<grid, block>>>(
        (const float4*)x, alpha1, beta1, alpha2, beta2, (float4*)out, n4);
}

// round 7
// speedup vs baseline: 1.1538x; 1.0004x over previous
#include <cuda_runtime.h>
#include <math.h>

// OnlineNeuron: T=4 two-compartment SNN recurrence, elementwise, f32.
// Pure HBM-streaming: 256 MB read + 256 MB write, irreducible.
// Shape = R2/R6 winner: one float4 per thread, four timestep LDG.128s
// front-batched (per-thread MLP=4), recurrence, four back-batched STG.128s.
// Round-7 probe: default cache policy (no .cs hints) — lets the LTS
// write-back path batch dirty sectors instead of evict-first streaming.
// Wall floor established at ~82 us (~6.25 TB/s sustained mixed R/W);
// MLP>4, 256-bit accesses, persistent grids all falsified (R3-R5).

#define T_STEPS 4

__device__ __forceinline__ float sigmoidf_(float v) {
    return 1.0f / (1.0f + expf(-v));
}

__global__ __launch_bounds__(512)
void online_neuron_kernel(const float4* __restrict__ x,
                          const float* __restrict__ alpha1,
                          const float* __restrict__ beta1,
                          const float* __restrict__ alpha2,
                          const float* __restrict__ beta2,
                          float4* __restrict__ out,
                          int n4)   // float4 count per timestep slab
{
    int i = blockIdx.x * blockDim.x + threadIdx.x;
    if (i >= n4) return;

    const long long stride = (long long)n4;   // float4 units between timesteps

    // ---- Front-batched loads: 4 independent LDG.128 in flight (MLP=4) ----
    float4 xt[T_STEPS];
    #pragma unroll
    for (int t = 0; t < T_STEPS; t++)
        xt[t] = x[(long long)t * stride + i];

    const float a1 = sigmoidf_(__ldg(alpha1)) - 0.5f;
    const float b1 = sigmoidf_(__ldg(beta1))  - 0.5f;
    const float a2 = sigmoidf_(__ldg(alpha2)) + 0.5f;
    const float b2 = sigmoidf_(__ldg(beta2))  + 0.5f;

    float4 vd = make_float4(0.f, 0.f, 0.f, 0.f);
    float4 vs = make_float4(0.5f, 0.5f, 0.5f, 0.5f);

    float4 o[T_STEPS];

    #pragma unroll
    for (int t = 0; t < T_STEPS; t++) {
        vd.x = a1 * vd.x + b1 * vs.x + xt[t].x;
        vd.y = a1 * vd.y + b1 * vs.y + xt[t].y;
        vd.z = a1 * vd.z + b1 * vs.z + xt[t].z;
        vd.w = a1 * vd.w + b1 * vs.w + xt[t].w;

        vs.x = a2 * vs.x + b2 * vd.x;
        vs.y = a2 * vs.y + b2 * vd.y;
        vs.z = a2 * vs.z + b2 * vd.z;
        vs.w = a2 * vs.w + b2 * vd.w;

        o[t].x = (vs.x >= 1.0f) ? 1.0f : 0.0f;
        o[t].y = (vs.y >= 1.0f) ? 1.0f : 0.0f;
        o[t].z = (vs.z >= 1.0f) ? 1.0f : 0.0f;
        o[t].w = (vs.w >= 1.0f) ? 1.0f : 0.0f;

        vs.x -= o[t].x;  vs.y -= o[t].y;  vs.z -= o[t].z;  vs.w -= o[t].w;
    }

    // ---- Back-batched stores (default write-back policy) ----
    #pragma unroll
    for (int t = 0; t < T_STEPS; t++)
        out[(long long)t * stride + i] = o[t];
}

extern "C" void kernel_launch(void* const* d_in, const int* in_sizes, int n_in,
                              void* d_out, int out_size)
{
    const float* x      = (const float*)d_in[0];
    const float* alpha1 = (const float*)d_in[1];
    const float* beta1  = (const float*)d_in[2];
    const float* alpha2 = (const float*)d_in[3];
    const float* beta2  = (const float*)d_in[4];
    float* out = (float*)d_out;

    const int n_total = in_sizes[0];          // 512*128*32*32 = 67,108,864
    const int n_slab  = n_total / T_STEPS;    // 16,777,216 floats per slab
    const int n4      = n_slab / 4;           // 4,194,304 float4 per slab

    const int block = 512;
    const int grid  = (n4 + block - 1) / block;   // 8192

    online_neuron_kernel<<<grid, block>>>(
        (const float4*)x, alpha1, beta1, alpha2, beta2, (float4*)out, n4);
}